// round 1
// baseline (speedup 1.0000x reference)
#include <cuda_runtime.h>
#include <math.h>

#define N_SAMPLES 65536
#define HDIM 128
#define GDIM 512   // 4*H
#define FCDIM 256

// ---------------- scratch (no runtime allocation allowed) ----------------
__device__ float g_h0[N_SAMPLES * HDIM];
__device__ float g_c0[N_SAMPLES * HDIM];
__device__ float g_h1[N_SAMPLES * HDIM];
__device__ float g_c1[N_SAMPLES * HDIM];
__device__ float g_hsum[N_SAMPLES * HDIM];
__device__ float g_feat[N_SAMPLES * 2 * HDIM];
__device__ float g_a0[N_SAMPLES * FCDIM];
__device__ float g_a1[N_SAMPLES * FCDIM];

// ---------------- fast-but-accurate activations (MUFU-based, ~2ulp) ------
__device__ __forceinline__ float sigf(float x) {
    float e = __expf(-x);
    return __fdividef(1.0f, 1.0f + e);
}
__device__ __forceinline__ float tanhf_fast(float x) {
    float ax = fabsf(x);
    float e = __expf(-2.0f * ax);
    float t = __fdividef(1.0f - e, 1.0f + e);
    return copysignf(t, x);
}

// ---------------------------------------------------------------------------
// Fused LSTM cell: gates[32x512] = A1@W1^T + A2@W2^T + bias (+ feat_t*wih for
// layer0), then elementwise LSTM update. A1/A2 nullable (null => skip GEMM).
// BM=32 rows/CTA, 512 gate cols, BK=16, 256 threads, 64 acc/thread.
// Thread (ty,tx): rows ty*4+i, cols tx+32*j  (j=0..15).
// Gate layout: cols [0,128)=i, [128,256)=f, [256,384)=g, [384,512)=o.
// => thread j=u holds i-gate of hidden unit hu=tx+32u, j=u+4 its f, j=u+8 its
//    g, j=u+12 its o  -> cell update is thread-local.
// ---------------------------------------------------------------------------
__global__ __launch_bounds__(256) void lstm_cell(
    const float* __restrict__ A1, const float* __restrict__ W1,
    const float* __restrict__ A2, const float* __restrict__ W2,
    const float* __restrict__ bias,
    const float* __restrict__ wih_vec,   // layer0: W_ih_l0 (512,1); else null
    const float* __restrict__ xin, const float* __restrict__ yin,
    float* __restrict__ hout, float* __restrict__ cbuf,
    float* __restrict__ hsumbuf, float* __restrict__ featbuf,
    int t)
{
    __shared__ float As[16][33];
    __shared__ float Bs[16][513];

    const int tid = threadIdx.x;
    const int tx  = tid & 31;
    const int ty  = tid >> 5;
    const int row0 = blockIdx.x * 32;

    float acc[4][16];

    // init with bias (and layer0's x-input rank-1 term)
    float bv[16];
    #pragma unroll
    for (int j = 0; j < 16; ++j) bv[j] = bias[tx + 32 * j];
    #pragma unroll
    for (int i = 0; i < 4; ++i)
        #pragma unroll
        for (int j = 0; j < 16; ++j) acc[i][j] = bv[j];

    if (wih_vec != nullptr) {
        float wv[16];
        #pragma unroll
        for (int j = 0; j < 16; ++j) wv[j] = wih_vec[tx + 32 * j];
        #pragma unroll
        for (int i = 0; i < 4; ++i) {
            int r = row0 + ty * 4 + i;
            float xn = 2.0f * xin[r] - 1.0f;
            float yn = 2.0f * yin[r] - 1.0f;
            float f;
            if      (t == 0) f = xn;
            else if (t == 1) f = yn;
            else if (t == 2) f = xn + yn;
            else if (t == 3) f = xn - yn;
            else if (t == 4) f = xn * yn;
            else             f = xn * xn + yn * yn;
            #pragma unroll
            for (int j = 0; j < 16; ++j) acc[i][j] += f * wv[j];
        }
    }

    const float* Aarr[2] = {A1, A2};
    const float* Warr[2] = {W1, W2};

    for (int pass = 0; pass < 2; ++pass) {
        const float* A = Aarr[pass];
        const float* W = Warr[pass];
        if (A == nullptr) continue;   // uniform across block
        for (int k0 = 0; k0 < 128; k0 += 16) {
            __syncthreads();
            // A tile: 32 rows x 16 k  (512 elems, 2/thread)
            {
                int idx = tid;
                #pragma unroll
                for (int it = 0; it < 2; ++it, idx += 256) {
                    int r = idx >> 4, kk = idx & 15;
                    As[kk][r] = A[(row0 + r) * HDIM + k0 + kk];
                }
            }
            // B tile: 512 cols x 16 k  (8192 elems, 32/thread)
            {
                #pragma unroll
                for (int it = 0; it < 32; ++it) {
                    int idx = tid + it * 256;
                    int col = idx >> 4, kk = idx & 15;
                    Bs[kk][col] = W[col * HDIM + k0 + kk];
                }
            }
            __syncthreads();
            #pragma unroll
            for (int kk = 0; kk < 16; ++kk) {
                float av[4], bvv[16];
                #pragma unroll
                for (int i = 0; i < 4; ++i) av[i] = As[kk][ty * 4 + i];
                #pragma unroll
                for (int j = 0; j < 16; ++j) bvv[j] = Bs[kk][tx + 32 * j];
                #pragma unroll
                for (int i = 0; i < 4; ++i)
                    #pragma unroll
                    for (int j = 0; j < 16; ++j)
                        acc[i][j] += av[i] * bvv[j];
            }
        }
    }

    // ---------------- LSTM cell epilogue (thread-local) ----------------
    #pragma unroll
    for (int i = 0; i < 4; ++i) {
        int r = row0 + ty * 4 + i;
        #pragma unroll
        for (int u = 0; u < 4; ++u) {
            int hu = tx + 32 * u;
            float ig = sigf(acc[i][u]);
            float fg = sigf(acc[i][u + 4]);
            float gg = tanhf_fast(acc[i][u + 8]);
            float og = sigf(acc[i][u + 12]);
            float cold = (t == 0) ? 0.0f : cbuf[r * HDIM + hu];
            float cn = fg * cold + ig * gg;
            float hn = og * tanhf_fast(cn);
            cbuf[r * HDIM + hu] = cn;
            hout[r * HDIM + hu] = hn;
            if (hsumbuf != nullptr) {
                float s = (t == 0) ? hn : (hsumbuf[r * HDIM + hu] + hn);
                hsumbuf[r * HDIM + hu] = s;
                if (t == 5 && featbuf != nullptr) {
                    featbuf[r * 2 * HDIM + hu] = hn;                       // last h
                    featbuf[r * 2 * HDIM + HDIM + hu] = s * (1.0f / 6.0f); // mean h
                }
            }
        }
    }
}

// ---------------------------------------------------------------------------
// Fused dense: out[32x256] = tanh(A[32x256] @ W[256x256]^T + b)
// Thread (ty,tx): rows ty*4+i, cols tx+32*j (j=0..7), 32 acc/thread.
// ---------------------------------------------------------------------------
__global__ __launch_bounds__(256) void dense_tanh(
    const float* __restrict__ A, const float* __restrict__ W,
    const float* __restrict__ bias, float* __restrict__ out)
{
    __shared__ float As[16][33];
    __shared__ float Bs[16][257];

    const int tid = threadIdx.x;
    const int tx  = tid & 31;
    const int ty  = tid >> 5;
    const int row0 = blockIdx.x * 32;

    float acc[4][8];
    #pragma unroll
    for (int j = 0; j < 8; ++j) {
        float bvj = bias[tx + 32 * j];
        #pragma unroll
        for (int i = 0; i < 4; ++i) acc[i][j] = bvj;
    }

    for (int k0 = 0; k0 < FCDIM; k0 += 16) {
        __syncthreads();
        {   // A tile: 32x16, 2/thread
            int idx = tid;
            #pragma unroll
            for (int it = 0; it < 2; ++it, idx += 256) {
                int r = idx >> 4, kk = idx & 15;
                As[kk][r] = A[(row0 + r) * FCDIM + k0 + kk];
            }
        }
        {   // B tile: 256x16, 16/thread
            #pragma unroll
            for (int it = 0; it < 16; ++it) {
                int idx = tid + it * 256;
                int col = idx >> 4, kk = idx & 15;
                Bs[kk][col] = W[col * FCDIM + k0 + kk];
            }
        }
        __syncthreads();
        #pragma unroll
        for (int kk = 0; kk < 16; ++kk) {
            float av[4], bvv[8];
            #pragma unroll
            for (int i = 0; i < 4; ++i) av[i] = As[kk][ty * 4 + i];
            #pragma unroll
            for (int j = 0; j < 8; ++j) bvv[j] = Bs[kk][tx + 32 * j];
            #pragma unroll
            for (int i = 0; i < 4; ++i)
                #pragma unroll
                for (int j = 0; j < 8; ++j)
                    acc[i][j] += av[i] * bvv[j];
        }
    }

    #pragma unroll
    for (int i = 0; i < 4; ++i) {
        int r = row0 + ty * 4 + i;
        #pragma unroll
        for (int j = 0; j < 8; ++j)
            out[r * FCDIM + tx + 32 * j] = tanhf_fast(acc[i][j]);
    }
}

// ---------------------------------------------------------------------------
// Output head: out[N x 4] = A[N x 256] @ Wout[4 x 256]^T + bout
// ---------------------------------------------------------------------------
__global__ __launch_bounds__(256) void out_head(
    const float* __restrict__ A, const float* __restrict__ W,
    const float* __restrict__ b, float* __restrict__ out)
{
    __shared__ float Ws[4][256];
    __shared__ float bs[4];
    const int tid = threadIdx.x;
    #pragma unroll
    for (int it = 0; it < 4; ++it) {
        int idx = tid + it * 256;
        Ws[idx >> 8][idx & 255] = W[idx];
    }
    if (tid < 4) bs[tid] = b[tid];
    __syncthreads();

    int row = blockIdx.x * 256 + tid;
    float a0 = bs[0], a1 = bs[1], a2 = bs[2], a3 = bs[3];
    const float4* Arow = (const float4*)(A + row * FCDIM);
    #pragma unroll 8
    for (int k4 = 0; k4 < 64; ++k4) {
        float4 v = Arow[k4];
        int k = k4 * 4;
        a0 += v.x * Ws[0][k] + v.y * Ws[0][k + 1] + v.z * Ws[0][k + 2] + v.w * Ws[0][k + 3];
        a1 += v.x * Ws[1][k] + v.y * Ws[1][k + 1] + v.z * Ws[1][k + 2] + v.w * Ws[1][k + 3];
        a2 += v.x * Ws[2][k] + v.y * Ws[2][k + 1] + v.z * Ws[2][k + 2] + v.w * Ws[2][k + 3];
        a3 += v.x * Ws[3][k] + v.y * Ws[3][k + 1] + v.z * Ws[3][k + 2] + v.w * Ws[3][k + 3];
    }
    float4 o; o.x = a0; o.y = a1; o.z = a2; o.w = a3;
    ((float4*)out)[row] = o;
}

// ---------------------------------------------------------------------------
extern "C" void kernel_launch(void* const* d_in, const int* in_sizes, int n_in,
                              void* d_out, int out_size)
{
    const float* x    = (const float*)d_in[0];
    const float* y    = (const float*)d_in[1];
    const float* Wih0 = (const float*)d_in[2];   // (512,1)
    const float* Whh0 = (const float*)d_in[3];   // (512,128)
    const float* b0   = (const float*)d_in[4];
    const float* Wih1 = (const float*)d_in[5];   // (512,128)
    const float* Whh1 = (const float*)d_in[6];   // (512,128)
    const float* b1   = (const float*)d_in[7];
    const float* Wd0  = (const float*)d_in[8];   // (256,256)
    const float* bd0  = (const float*)d_in[9];
    const float* Wd1  = (const float*)d_in[10];
    const float* bd1  = (const float*)d_in[11];
    const float* Wd2  = (const float*)d_in[12];
    const float* bd2  = (const float*)d_in[13];
    const float* Wo   = (const float*)d_in[14];  // (4,256)
    const float* bo   = (const float*)d_in[15];
    float* out = (float*)d_out;

    float *h0, *c0, *h1, *c1, *hs, *ft, *a0, *a1;
    cudaGetSymbolAddress((void**)&h0, g_h0);
    cudaGetSymbolAddress((void**)&c0, g_c0);
    cudaGetSymbolAddress((void**)&h1, g_h1);
    cudaGetSymbolAddress((void**)&c1, g_c1);
    cudaGetSymbolAddress((void**)&hs, g_hsum);
    cudaGetSymbolAddress((void**)&ft, g_feat);
    cudaGetSymbolAddress((void**)&a0, g_a0);
    cudaGetSymbolAddress((void**)&a1, g_a1);

    const int grid = N_SAMPLES / 32;

    for (int t = 0; t < 6; ++t) {
        // layer 0: gates = feat_t * Wih0 + h0 @ Whh0^T + b0
        lstm_cell<<<grid, 256>>>(nullptr, nullptr,
                                 (t == 0) ? nullptr : h0, Whh0,
                                 b0, Wih0, x, y,
                                 h0, c0, nullptr, nullptr, t);
        // layer 1: gates = h0 @ Wih1^T + h1 @ Whh1^T + b1
        lstm_cell<<<grid, 256>>>(h0, Wih1,
                                 (t == 0) ? nullptr : h1, Whh1,
                                 b1, nullptr, nullptr, nullptr,
                                 h1, c1, hs, ft, t);
    }

    dense_tanh<<<grid, 256>>>(ft, Wd0, bd0, a0);
    dense_tanh<<<grid, 256>>>(a0, Wd1, bd1, a1);
    dense_tanh<<<grid, 256>>>(a1, Wd2, bd2, a0);
    out_head<<<N_SAMPLES / 256, 256>>>(a0, Wo, bo, out);
}

// round 2
// speedup vs baseline: 2.3213x; 2.3213x over previous
#include <cuda_runtime.h>
#include <math.h>

#define NS 65536
typedef unsigned long long u64;

// ---------------- packed f32x2 helpers (SASS FFMA2 path) -----------------
__device__ __forceinline__ u64 pk2(float a, float b) {
    u64 r; asm("mov.b64 %0,{%1,%2};" : "=l"(r) : "f"(a), "f"(b)); return r;
}
__device__ __forceinline__ void upk2(u64 v, float& a, float& b) {
    asm("mov.b64 {%0,%1},%2;" : "=f"(a), "=f"(b) : "l"(v));
}
__device__ __forceinline__ void ffma2(u64& d, u64 a, u64 b) {
    asm("fma.rn.f32x2 %0,%1,%2,%0;" : "+l"(d) : "l"(a), "l"(b));
}

// ---------------- fast activations (MUFU, ~2ulp) --------------------------
__device__ __forceinline__ float sigf(float x) {
    float e = __expf(-x); return __fdividef(1.f, 1.f + e);
}
__device__ __forceinline__ float tanhf_fast(float x) {
    float ax = fabsf(x);
    float e = __expf(-2.f * ax);
    float t = __fdividef(1.f - e, 1.f + e);
    return copysignf(t, x);
}

// ---------------------------------------------------------------------------
// Shared-memory GEMM pass: acc[32 rows x NCOL cols] += A[32 x K] @ W[NCOL x K]^T
// A lives in shared (row stride 258 floats). W streamed global->shared in
// BK=16 tiles (float4 loads). Thread (ty,tx) owns rows ty*4+i and column
// pairs (2*tx+64*p, +1), p < NCOL/64. Inner product via packed FFMA2.
// ---------------------------------------------------------------------------
template<int K, int NCOL>
__device__ __forceinline__ void gemm_pass(const float* __restrict__ W,
                                          const float* __restrict__ Abase,
                                          u64 (&acc)[4][8],
                                          float* Bs, int tid, int tx, int ty)
{
    constexpr int P = NCOL / 64;
    for (int k0 = 0; k0 < K; k0 += 16) {
        __syncthreads();
        const float4* W4 = (const float4*)W;
        #pragma unroll
        for (int it = 0; it < NCOL / 64; ++it) {
            int v = tid + it * 256;
            int col = v >> 2, q = v & 3;
            float4 f = W4[col * (K / 4) + (k0 >> 2) + q];
            float* bp = Bs + (q * 4) * 514 + col;
            bp[0] = f.x; bp[514] = f.y; bp[1028] = f.z; bp[1542] = f.w;
        }
        __syncthreads();
        #pragma unroll
        for (int kk = 0; kk < 16; ++kk) {
            u64 a2[4];
            #pragma unroll
            for (int i = 0; i < 4; ++i) {
                float av = Abase[(ty * 4 + i) * 258 + k0 + kk];  // LDS broadcast
                a2[i] = pk2(av, av);
            }
            const u64* brow = (const u64*)(Bs + kk * 514);
            #pragma unroll
            for (int p = 0; p < P; ++p) {
                u64 b = brow[tx + 32 * p];                        // LDS.64
                #pragma unroll
                for (int i = 0; i < 4; ++i) ffma2(acc[i][p], a2[i], b);
            }
        }
    }
}

// ---------------------------------------------------------------------------
// One persistent kernel: CTA = 32 samples through the whole network.
// smem: Bs[16][514] | R2[32][258]{h0|c0 -> dense pong} | A0[32][258]{h1|hsum -> feat/ping}
// ---------------------------------------------------------------------------
__global__ void __launch_bounds__(256, 2) fused_net(
    const float* __restrict__ x, const float* __restrict__ y,
    const float* __restrict__ Wih0, const float* __restrict__ Whh0, const float* __restrict__ b0,
    const float* __restrict__ Wih1, const float* __restrict__ Whh1, const float* __restrict__ b1,
    const float* __restrict__ Wd0, const float* __restrict__ bd0,
    const float* __restrict__ Wd1, const float* __restrict__ bd1,
    const float* __restrict__ Wd2, const float* __restrict__ bd2,
    const float* __restrict__ Wo,  const float* __restrict__ bo,
    float* __restrict__ out)
{
    extern __shared__ float smem[];
    float* Bs = smem;                 // 16*514  = 8224 floats
    float* R2 = smem + 16 * 514;      // 32*258  = 8256 floats
    float* A0 = R2 + 32 * 258;        // 32*258  = 8256 floats

    const int tid = threadIdx.x, tx = tid & 31, ty = tid >> 5;
    const int row0 = blockIdx.x * 32;

    float xn[4], yn[4];
    #pragma unroll
    for (int i = 0; i < 4; ++i) {
        int r = row0 + ty * 4 + i;
        xn[i] = 2.f * x[r] - 1.f;
        yn[i] = 2.f * y[r] - 1.f;
    }

    float c1r[16];
    #pragma unroll
    for (int i = 0; i < 16; ++i) c1r[i] = 0.f;

    u64 acc[4][8];

    for (int t = 0; t < 6; ++t) {
        // ======================= layer 0 =======================
        {
            u64 bv[8], wv[8];
            #pragma unroll
            for (int p = 0; p < 8; ++p) {
                int c = 2 * tx + 64 * p;
                bv[p] = *(const u64*)(b0 + c);
                wv[p] = *(const u64*)(Wih0 + c);
            }
            #pragma unroll
            for (int i = 0; i < 4; ++i) {
                float f;
                if      (t == 0) f = xn[i];
                else if (t == 1) f = yn[i];
                else if (t == 2) f = xn[i] + yn[i];
                else if (t == 3) f = xn[i] - yn[i];
                else if (t == 4) f = xn[i] * yn[i];
                else             f = xn[i] * xn[i] + yn[i] * yn[i];
                u64 f2 = pk2(f, f);
                #pragma unroll
                for (int p = 0; p < 8; ++p) { acc[i][p] = bv[p]; ffma2(acc[i][p], f2, wv[p]); }
            }
            if (t > 0) gemm_pass<128, 512>(Whh0, R2, acc, Bs, tid, tx, ty);
            __syncthreads();   // all reads of old h0 done before overwrite
            #pragma unroll
            for (int i = 0; i < 4; ++i) {
                float* row = R2 + (ty * 4 + i) * 258;
                #pragma unroll
                for (int q = 0; q < 2; ++q) {
                    int u0 = 2 * tx + 64 * q;
                    float gi0, gi1, gf0, gf1, gg0, gg1, go0, go1;
                    upk2(acc[i][q],     gi0, gi1);
                    upk2(acc[i][q + 2], gf0, gf1);
                    upk2(acc[i][q + 4], gg0, gg1);
                    upk2(acc[i][q + 6], go0, go1);
                    float co0 = 0.f, co1 = 0.f;
                    if (t > 0) { float2 cc = *(float2*)(row + 128 + u0); co0 = cc.x; co1 = cc.y; }
                    float cn0 = sigf(gf0) * co0 + sigf(gi0) * tanhf_fast(gg0);
                    float cn1 = sigf(gf1) * co1 + sigf(gi1) * tanhf_fast(gg1);
                    float hn0 = sigf(go0) * tanhf_fast(cn0);
                    float hn1 = sigf(go1) * tanhf_fast(cn1);
                    *(float2*)(row + 128 + u0) = make_float2(cn0, cn1);
                    *(float2*)(row + u0)       = make_float2(hn0, hn1);
                }
            }
        }
        // ======================= layer 1 =======================
        {
            #pragma unroll
            for (int i = 0; i < 4; ++i)
                #pragma unroll
                for (int p = 0; p < 8; ++p) acc[i][p] = *(const u64*)(b1 + 2 * tx + 64 * p);
            gemm_pass<128, 512>(Wih1, R2, acc, Bs, tid, tx, ty);          // input = new h0
            if (t > 0) gemm_pass<128, 512>(Whh1, A0, acc, Bs, tid, tx, ty); // recurrent h1
            __syncthreads();   // all reads of old h1 done before overwrite
            #pragma unroll
            for (int i = 0; i < 4; ++i) {
                float* row = A0 + (ty * 4 + i) * 258;
                #pragma unroll
                for (int q = 0; q < 2; ++q) {
                    int u0 = 2 * tx + 64 * q;
                    float gi0, gi1, gf0, gf1, gg0, gg1, go0, go1;
                    upk2(acc[i][q],     gi0, gi1);
                    upk2(acc[i][q + 2], gf0, gf1);
                    upk2(acc[i][q + 4], gg0, gg1);
                    upk2(acc[i][q + 6], go0, go1);
                    float co0 = c1r[i * 4 + q * 2], co1 = c1r[i * 4 + q * 2 + 1];
                    float cn0 = sigf(gf0) * co0 + sigf(gi0) * tanhf_fast(gg0);
                    float cn1 = sigf(gf1) * co1 + sigf(gi1) * tanhf_fast(gg1);
                    float hn0 = sigf(go0) * tanhf_fast(cn0);
                    float hn1 = sigf(go1) * tanhf_fast(cn1);
                    c1r[i * 4 + q * 2]     = cn0;
                    c1r[i * 4 + q * 2 + 1] = cn1;
                    *(float2*)(row + u0) = make_float2(hn0, hn1);        // h1 (feat cols 0-127)
                    float s0, s1;
                    if (t == 0) { s0 = hn0; s1 = hn1; }
                    else { float2 sv = *(float2*)(row + 128 + u0); s0 = sv.x + hn0; s1 = sv.y + hn1; }
                    if (t == 5) { s0 *= (1.f / 6.f); s1 *= (1.f / 6.f); }
                    *(float2*)(row + 128 + u0) = make_float2(s0, s1);    // mean (feat cols 128-255)
                }
            }
        }
    }

    // ======================= dense stack =======================
    const float* Wds[3] = {Wd0, Wd1, Wd2};
    const float* bds[3] = {bd0, bd1, bd2};
    float* ping = A0;   // feat
    float* pong = R2;   // h0/c0 dead
    for (int l = 0; l < 3; ++l) {
        #pragma unroll
        for (int i = 0; i < 4; ++i)
            #pragma unroll
            for (int p = 0; p < 4; ++p) acc[i][p] = *(const u64*)(bds[l] + 2 * tx + 64 * p);
        gemm_pass<256, 256>(Wds[l], ping, acc, Bs, tid, tx, ty);
        __syncthreads();
        #pragma unroll
        for (int i = 0; i < 4; ++i) {
            float* row = pong + (ty * 4 + i) * 258;
            #pragma unroll
            for (int p = 0; p < 4; ++p) {
                float a0v, a1v; upk2(acc[i][p], a0v, a1v);
                *(float2*)(row + 2 * tx + 64 * p) =
                    make_float2(tanhf_fast(a0v), tanhf_fast(a1v));
            }
        }
        float* tmp = ping; ping = pong; pong = tmp;
    }
    __syncthreads();

    // ======================= output head =======================
    // ping == R2 holds dense2 output [32][256] (stride 258)
    if (tid < 128) {
        int r = tid >> 2, o = tid & 3;
        const float* a = ping + r * 258;
        const float* w = Wo + o * 256;
        float s0 = 0.f, s1 = 0.f, s2 = 0.f, s3 = 0.f;
        #pragma unroll 4
        for (int k = 0; k < 256; k += 4) {
            s0 += a[k]     * w[k];
            s1 += a[k + 1] * w[k + 1];
            s2 += a[k + 2] * w[k + 2];
            s3 += a[k + 3] * w[k + 3];
        }
        out[(row0 + r) * 4 + o] = bo[o] + ((s0 + s1) + (s2 + s3));
    }
}

// ---------------------------------------------------------------------------
extern "C" void kernel_launch(void* const* d_in, const int* in_sizes, int n_in,
                              void* d_out, int out_size)
{
    const float* x    = (const float*)d_in[0];
    const float* y    = (const float*)d_in[1];
    const float* Wih0 = (const float*)d_in[2];
    const float* Whh0 = (const float*)d_in[3];
    const float* b0   = (const float*)d_in[4];
    const float* Wih1 = (const float*)d_in[5];
    const float* Whh1 = (const float*)d_in[6];
    const float* b1   = (const float*)d_in[7];
    const float* Wd0  = (const float*)d_in[8];
    const float* bd0  = (const float*)d_in[9];
    const float* Wd1  = (const float*)d_in[10];
    const float* bd1  = (const float*)d_in[11];
    const float* Wd2  = (const float*)d_in[12];
    const float* bd2  = (const float*)d_in[13];
    const float* Wo   = (const float*)d_in[14];
    const float* bo   = (const float*)d_in[15];
    float* out = (float*)d_out;

    const int smem = (16 * 514 + 2 * 32 * 258) * (int)sizeof(float);  // 98944 B
    cudaFuncSetAttribute(fused_net, cudaFuncAttributeMaxDynamicSharedMemorySize, smem);

    fused_net<<<NS / 32, 256, smem>>>(x, y,
                                      Wih0, Whh0, b0, Wih1, Whh1, b1,
                                      Wd0, bd0, Wd1, bd1, Wd2, bd2,
                                      Wo, bo, out);
}

// round 3
// speedup vs baseline: 2.3243x; 1.0013x over previous
#include <cuda_runtime.h>
#include <math.h>

#define NS 65536
typedef unsigned long long u64;

// ---------------- packed f32x2 helpers (SASS FFMA2 path) -----------------
__device__ __forceinline__ u64 pk2(float a, float b) {
    u64 r; asm("mov.b64 %0,{%1,%2};" : "=l"(r) : "f"(a), "f"(b)); return r;
}
__device__ __forceinline__ void upk2(u64 v, float& a, float& b) {
    asm("mov.b64 {%0,%1},%2;" : "=f"(a), "=f"(b) : "l"(v));
}
__device__ __forceinline__ void ffma2(u64& d, u64 a, u64 b) {
    asm("fma.rn.f32x2 %0,%1,%2,%0;" : "+l"(d) : "l"(a), "l"(b));
}

// ---------------- fast activations (MUFU, ~2ulp) --------------------------
__device__ __forceinline__ float sigf(float x) {
    float e = __expf(-x); return __fdividef(1.f, 1.f + e);
}
__device__ __forceinline__ float tanhf_fast(float x) {
    float ax = fabsf(x);
    float e = __expf(-2.f * ax);
    float t = __fdividef(1.f - e, 1.f + e);
    return copysignf(t, x);
}

// ---------------------------------------------------------------------------
// Shared-memory GEMM pass: acc[32 rows x NCOL cols] += A[32 x K] @ W[NCOL x K]^T
// A lives in shared (row stride 258 floats). W streamed global->shared in
// BK=16 tiles (float4 loads). Thread (ty,tx) owns rows ty*4+i and column
// pairs (2*tx+64*p, +1), p < NCOL/64. Inner product via packed FFMA2.
// ---------------------------------------------------------------------------
template<int K, int NCOL>
__device__ __forceinline__ void gemm_pass(const float* __restrict__ W,
                                          const float* __restrict__ Abase,
                                          u64 (&acc)[4][8],
                                          float* Bs, int tid, int tx, int ty)
{
    constexpr int P = NCOL / 64;
    for (int k0 = 0; k0 < K; k0 += 16) {
        __syncthreads();
        const float4* W4 = (const float4*)W;
        #pragma unroll
        for (int it = 0; it < NCOL / 64; ++it) {
            int v = tid + it * 256;
            int col = v >> 2, q = v & 3;
            float4 f = W4[col * (K / 4) + (k0 >> 2) + q];
            float* bp = Bs + (q * 4) * 514 + col;
            bp[0] = f.x; bp[514] = f.y; bp[1028] = f.z; bp[1542] = f.w;
        }
        __syncthreads();
        #pragma unroll
        for (int kk = 0; kk < 16; ++kk) {
            u64 a2[4];
            #pragma unroll
            for (int i = 0; i < 4; ++i) {
                float av = Abase[(ty * 4 + i) * 258 + k0 + kk];  // LDS broadcast
                a2[i] = pk2(av, av);
            }
            const u64* brow = (const u64*)(Bs + kk * 514);
            #pragma unroll
            for (int p = 0; p < P; ++p) {
                u64 b = brow[tx + 32 * p];                        // LDS.64
                #pragma unroll
                for (int i = 0; i < 4; ++i) ffma2(acc[i][p], a2[i], b);
            }
        }
    }
}

// ---------------------------------------------------------------------------
// One persistent kernel: CTA = 32 samples through the whole network.
// smem: Bs[16][514] | R2[32][258]{h0|c0 -> dense pong} | A0[32][258]{h1|hsum -> feat/ping}
// ---------------------------------------------------------------------------
__global__ void __launch_bounds__(256, 2) fused_net(
    const float* __restrict__ x, const float* __restrict__ y,
    const float* __restrict__ Wih0, const float* __restrict__ Whh0, const float* __restrict__ b0,
    const float* __restrict__ Wih1, const float* __restrict__ Whh1, const float* __restrict__ b1,
    const float* __restrict__ Wd0, const float* __restrict__ bd0,
    const float* __restrict__ Wd1, const float* __restrict__ bd1,
    const float* __restrict__ Wd2, const float* __restrict__ bd2,
    const float* __restrict__ Wo,  const float* __restrict__ bo,
    float* __restrict__ out)
{
    extern __shared__ float smem[];
    float* Bs = smem;                 // 16*514  = 8224 floats
    float* R2 = smem + 16 * 514;      // 32*258  = 8256 floats
    float* A0 = R2 + 32 * 258;        // 32*258  = 8256 floats

    const int tid = threadIdx.x, tx = tid & 31, ty = tid >> 5;
    const int row0 = blockIdx.x * 32;

    float xn[4], yn[4];
    #pragma unroll
    for (int i = 0; i < 4; ++i) {
        int r = row0 + ty * 4 + i;
        xn[i] = 2.f * x[r] - 1.f;
        yn[i] = 2.f * y[r] - 1.f;
    }

    float c1r[16];
    #pragma unroll
    for (int i = 0; i < 16; ++i) c1r[i] = 0.f;

    u64 acc[4][8];

    for (int t = 0; t < 6; ++t) {
        // ======================= layer 0 =======================
        {
            u64 bv[8], wv[8];
            #pragma unroll
            for (int p = 0; p < 8; ++p) {
                int c = 2 * tx + 64 * p;
                bv[p] = *(const u64*)(b0 + c);
                wv[p] = *(const u64*)(Wih0 + c);
            }
            #pragma unroll
            for (int i = 0; i < 4; ++i) {
                float f;
                if      (t == 0) f = xn[i];
                else if (t == 1) f = yn[i];
                else if (t == 2) f = xn[i] + yn[i];
                else if (t == 3) f = xn[i] - yn[i];
                else if (t == 4) f = xn[i] * yn[i];
                else             f = xn[i] * xn[i] + yn[i] * yn[i];
                u64 f2 = pk2(f, f);
                #pragma unroll
                for (int p = 0; p < 8; ++p) { acc[i][p] = bv[p]; ffma2(acc[i][p], f2, wv[p]); }
            }
            if (t > 0) gemm_pass<128, 512>(Whh0, R2, acc, Bs, tid, tx, ty);
            __syncthreads();   // all reads of old h0 done before overwrite
            #pragma unroll
            for (int i = 0; i < 4; ++i) {
                float* row = R2 + (ty * 4 + i) * 258;
                #pragma unroll
                for (int q = 0; q < 2; ++q) {
                    int u0 = 2 * tx + 64 * q;
                    float gi0, gi1, gf0, gf1, gg0, gg1, go0, go1;
                    upk2(acc[i][q],     gi0, gi1);
                    upk2(acc[i][q + 2], gf0, gf1);
                    upk2(acc[i][q + 4], gg0, gg1);
                    upk2(acc[i][q + 6], go0, go1);
                    float co0 = 0.f, co1 = 0.f;
                    if (t > 0) { float2 cc = *(float2*)(row + 128 + u0); co0 = cc.x; co1 = cc.y; }
                    float cn0 = sigf(gf0) * co0 + sigf(gi0) * tanhf_fast(gg0);
                    float cn1 = sigf(gf1) * co1 + sigf(gi1) * tanhf_fast(gg1);
                    float hn0 = sigf(go0) * tanhf_fast(cn0);
                    float hn1 = sigf(go1) * tanhf_fast(cn1);
                    *(float2*)(row + 128 + u0) = make_float2(cn0, cn1);
                    *(float2*)(row + u0)       = make_float2(hn0, hn1);
                }
            }
        }
        // ======================= layer 1 =======================
        {
            #pragma unroll
            for (int i = 0; i < 4; ++i)
                #pragma unroll
                for (int p = 0; p < 8; ++p) acc[i][p] = *(const u64*)(b1 + 2 * tx + 64 * p);
            gemm_pass<128, 512>(Wih1, R2, acc, Bs, tid, tx, ty);          // input = new h0
            if (t > 0) gemm_pass<128, 512>(Whh1, A0, acc, Bs, tid, tx, ty); // recurrent h1
            __syncthreads();   // all reads of old h1 done before overwrite
            #pragma unroll
            for (int i = 0; i < 4; ++i) {
                float* row = A0 + (ty * 4 + i) * 258;
                #pragma unroll
                for (int q = 0; q < 2; ++q) {
                    int u0 = 2 * tx + 64 * q;
                    float gi0, gi1, gf0, gf1, gg0, gg1, go0, go1;
                    upk2(acc[i][q],     gi0, gi1);
                    upk2(acc[i][q + 2], gf0, gf1);
                    upk2(acc[i][q + 4], gg0, gg1);
                    upk2(acc[i][q + 6], go0, go1);
                    float co0 = c1r[i * 4 + q * 2], co1 = c1r[i * 4 + q * 2 + 1];
                    float cn0 = sigf(gf0) * co0 + sigf(gi0) * tanhf_fast(gg0);
                    float cn1 = sigf(gf1) * co1 + sigf(gi1) * tanhf_fast(gg1);
                    float hn0 = sigf(go0) * tanhf_fast(cn0);
                    float hn1 = sigf(go1) * tanhf_fast(cn1);
                    c1r[i * 4 + q * 2]     = cn0;
                    c1r[i * 4 + q * 2 + 1] = cn1;
                    *(float2*)(row + u0) = make_float2(hn0, hn1);        // h1 (feat cols 0-127)
                    float s0, s1;
                    if (t == 0) { s0 = hn0; s1 = hn1; }
                    else { float2 sv = *(float2*)(row + 128 + u0); s0 = sv.x + hn0; s1 = sv.y + hn1; }
                    if (t == 5) { s0 *= (1.f / 6.f); s1 *= (1.f / 6.f); }
                    *(float2*)(row + 128 + u0) = make_float2(s0, s1);    // mean (feat cols 128-255)
                }
            }
        }
    }

    // ======================= dense stack =======================
    const float* Wds[3] = {Wd0, Wd1, Wd2};
    const float* bds[3] = {bd0, bd1, bd2};
    float* ping = A0;   // feat
    float* pong = R2;   // h0/c0 dead
    for (int l = 0; l < 3; ++l) {
        #pragma unroll
        for (int i = 0; i < 4; ++i)
            #pragma unroll
            for (int p = 0; p < 4; ++p) acc[i][p] = *(const u64*)(bds[l] + 2 * tx + 64 * p);
        gemm_pass<256, 256>(Wds[l], ping, acc, Bs, tid, tx, ty);
        __syncthreads();
        #pragma unroll
        for (int i = 0; i < 4; ++i) {
            float* row = pong + (ty * 4 + i) * 258;
            #pragma unroll
            for (int p = 0; p < 4; ++p) {
                float a0v, a1v; upk2(acc[i][p], a0v, a1v);
                *(float2*)(row + 2 * tx + 64 * p) =
                    make_float2(tanhf_fast(a0v), tanhf_fast(a1v));
            }
        }
        float* tmp = ping; ping = pong; pong = tmp;
    }
    __syncthreads();

    // ======================= output head =======================
    // ping == R2 holds dense2 output [32][256] (stride 258)
    if (tid < 128) {
        int r = tid >> 2, o = tid & 3;
        const float* a = ping + r * 258;
        const float* w = Wo + o * 256;
        float s0 = 0.f, s1 = 0.f, s2 = 0.f, s3 = 0.f;
        #pragma unroll 4
        for (int k = 0; k < 256; k += 4) {
            s0 += a[k]     * w[k];
            s1 += a[k + 1] * w[k + 1];
            s2 += a[k + 2] * w[k + 2];
            s3 += a[k + 3] * w[k + 3];
        }
        out[(row0 + r) * 4 + o] = bo[o] + ((s0 + s1) + (s2 + s3));
    }
}

// ---------------------------------------------------------------------------
extern "C" void kernel_launch(void* const* d_in, const int* in_sizes, int n_in,
                              void* d_out, int out_size)
{
    const float* x    = (const float*)d_in[0];
    const float* y    = (const float*)d_in[1];
    const float* Wih0 = (const float*)d_in[2];
    const float* Whh0 = (const float*)d_in[3];
    const float* b0   = (const float*)d_in[4];
    const float* Wih1 = (const float*)d_in[5];
    const float* Whh1 = (const float*)d_in[6];
    const float* b1   = (const float*)d_in[7];
    const float* Wd0  = (const float*)d_in[8];
    const float* bd0  = (const float*)d_in[9];
    const float* Wd1  = (const float*)d_in[10];
    const float* bd1  = (const float*)d_in[11];
    const float* Wd2  = (const float*)d_in[12];
    const float* bd2  = (const float*)d_in[13];
    const float* Wo   = (const float*)d_in[14];
    const float* bo   = (const float*)d_in[15];
    float* out = (float*)d_out;

    const int smem = (16 * 514 + 2 * 32 * 258) * (int)sizeof(float);  // 98944 B
    cudaFuncSetAttribute(fused_net, cudaFuncAttributeMaxDynamicSharedMemorySize, smem);

    fused_net<<<NS / 32, 256, smem>>>(x, y,
                                      Wih0, Whh0, b0, Wih1, Whh1, b1,
                                      Wd0, bd0, Wd1, bd1, Wd2, bd2,
                                      Wo, bo, out);
}